// round 3
// baseline (speedup 1.0000x reference)
#include <cuda_runtime.h>
#include <cuda_bf16.h>
#include <math.h>

#define MAXN   1024
#define NSHIFT 27          // nshift_real = 1 -> 3^3
#define NKDIM  17          // nshift_recip = 8 -> 17 per dim
#define NKHALF 2456        // (17^3 - 1) / 2 ; inversion symmetry
#define NT     10          // NTYPES

// -------- device globals (scratch) --------
__device__ float4 g_posq[MAXN];          // x,y,z,q
__device__ float  g_sig[MAXN];
__device__ int    g_type[MAXN];
__device__ float  g_gamtab[NT*NT];       // 1/(sqrt(2)*gamma_ij) per type pair
__device__ float4 g_shift[NSHIFT];       // xyz = shift vector, w = |shift|^2
__device__ float  g_recipm[9];           // 2*pi*inv(cell)^T rows
__device__ float  g_eta, g_inv_s2eta, g_cut2_real, g_cut2_recip;
__device__ double g_vol;
__device__ double g_acc_real, g_acc_recip;

// fast erfc: Abramowitz & Stegun 7.1.26, |abs err| <= 1.5e-7
__device__ __forceinline__ float erfc_fast(float x)
{
    float t = __fdividef(1.0f, fmaf(0.3275911f, x, 1.0f));
    float p = t * fmaf(t, fmaf(t, fmaf(t, fmaf(t, 1.061405429f, -1.453152027f),
                        1.421413741f), -0.284496736f), 0.254829592f);
    return p * __expf(-x * x);
}

// -------- setup (1 thread, double precision) --------
__global__ void k_setup(const float* __restrict__ cell,
                        const float* __restrict__ sigtab, int n)
{
    double c00 = cell[0], c01 = cell[1], c02 = cell[2];
    double c10 = cell[3], c11 = cell[4], c12 = cell[5];
    double c20 = cell[6], c21 = cell[7], c22 = cell[8];

    double cof00 =  (c11*c22 - c12*c21);
    double cof01 = -(c10*c22 - c12*c20);
    double cof02 =  (c10*c21 - c11*c20);
    double cof10 = -(c01*c22 - c02*c21);
    double cof11 =  (c00*c22 - c02*c20);
    double cof12 = -(c00*c21 - c01*c20);
    double cof20 =  (c01*c12 - c02*c11);
    double cof21 = -(c00*c12 - c02*c10);
    double cof22 =  (c00*c11 - c01*c10);

    double det = c00*cof00 + c01*cof01 + c02*cof02;
    double vol = fabs(det);
    g_vol = vol;

    const double TWO_PI = 6.283185307179586476925286766559;
    double eta = pow(vol*vol / (double)n, 1.0/6.0) / sqrt(TWO_PI);
    double sqrt2log = sqrt(-2.0 * log(1e-8));
    double cut_r = sqrt2log * eta;
    double cut_k = sqrt2log / eta;

    g_eta        = (float)eta;
    g_inv_s2eta  = (float)(1.0 / (1.4142135623730951 * eta));
    g_cut2_real  = (float)(cut_r * cut_r);
    g_cut2_recip = (float)(cut_k * cut_k);

    double inv_det = 1.0 / det;
    g_recipm[0] = (float)(TWO_PI * cof00 * inv_det);
    g_recipm[1] = (float)(TWO_PI * cof01 * inv_det);
    g_recipm[2] = (float)(TWO_PI * cof02 * inv_det);
    g_recipm[3] = (float)(TWO_PI * cof10 * inv_det);
    g_recipm[4] = (float)(TWO_PI * cof11 * inv_det);
    g_recipm[5] = (float)(TWO_PI * cof12 * inv_det);
    g_recipm[6] = (float)(TWO_PI * cof20 * inv_det);
    g_recipm[7] = (float)(TWO_PI * cof21 * inv_det);
    g_recipm[8] = (float)(TWO_PI * cof22 * inv_det);

    int idx = 0;
    for (int sx = -1; sx <= 1; sx++)
        for (int sy = -1; sy <= 1; sy++)
            for (int sz = -1; sz <= 1; sz++) {
                double x = sx*c00 + sy*c10 + sz*c20;
                double y = sx*c01 + sy*c11 + sz*c21;
                double z = sx*c02 + sy*c12 + sz*c22;
                g_shift[idx] = make_float4((float)x, (float)y, (float)z,
                                           (float)(x*x + y*y + z*z));
                idx++;
            }

    // per-type-pair 1/(sqrt(2)*gamma)
    for (int a = 0; a < NT; a++)
        for (int b = 0; b < NT; b++) {
            double sa = sigtab[a], sb = sigtab[b];
            g_gamtab[a*NT + b] = (float)(1.0 / sqrt(2.0*(sa*sa + sb*sb)));
        }

    g_acc_real  = 0.0;
    g_acc_recip = 0.0;
}

// -------- prep: pack per-atom data --------
__global__ void k_prep(const float* __restrict__ pos, const float* __restrict__ charges,
                       const float* __restrict__ sigma_table, const int* __restrict__ species,
                       int n)
{
    int i = blockIdx.x * blockDim.x + threadIdx.x;
    if (i < n) {
        g_posq[i] = make_float4(pos[3*i], pos[3*i+1], pos[3*i+2], charges[i]);
        int sp = species[i];
        g_sig[i]  = sigma_table[sp];
        g_type[i] = sp;
    }
}

// -------- real-space: strictly-lower-triangular pairs, mask compaction --------
__global__ void __launch_bounds__(512) k_real(int n, int npairs)
{
    __shared__ float4 sh_shift[NSHIFT];
    __shared__ double sh_red[16];
    if (threadIdx.x < NSHIFT) sh_shift[threadIdx.x] = g_shift[threadIdx.x];
    __syncthreads();

    int t = blockIdx.x * blockDim.x + threadIdx.x;
    float contrib = 0.f;

    if (t < npairs) {
        // decode t -> (i, j), j < i  (i >= 1)
        // 8t+1 <= 8*294528+1 < 2^24 -> exact in fp32
        int i = (int)((1.0f + sqrtf(1.0f + 8.0f * (float)t)) * 0.5f);
        // correction for rounding
        while ((long long)i * (i - 1) / 2 > t) i--;
        while ((long long)(i + 1) * i / 2 <= t) i++;
        int j = t - i * (i - 1) / 2;

        float4 a = g_posq[i];
        float4 b = g_posq[j];
        float dx = b.x - a.x, dy = b.y - a.y, dz = b.z - a.z;
        float inv_s2gam = g_gamtab[g_type[i]*NT + g_type[j]];
        float inv_s2eta = g_inv_s2eta;
        float cut2      = g_cut2_real;

        // pass 1: cheap mask build
        unsigned mask = 0u;
        #pragma unroll
        for (int m = 0; m < NSHIFT; m++) {
            float ddx = dx + sh_shift[m].x;
            float ddy = dy + sh_shift[m].y;
            float ddz = dz + sh_shift[m].z;
            float r2  = fmaf(ddx, ddx, fmaf(ddy, ddy, ddz*ddz));
            if (r2 > 1e-16f && r2 < cut2) mask |= (1u << m);
        }

        // pass 2: expensive math only on hits
        float s = 0.f;
        while (mask) {
            int m = __ffs(mask) - 1;
            mask &= mask - 1;
            float4 sm = sh_shift[m];
            float ddx = dx + sm.x;
            float ddy = dy + sm.y;
            float ddz = dz + sm.z;
            float r2  = fmaf(ddx, ddx, fmaf(ddy, ddy, ddz*ddz));
            float rinv = rsqrtf(r2);
            float r    = r2 * rinv;
            s = fmaf(erfc_fast(r * inv_s2eta) - erfc_fast(r * inv_s2gam), rinv, s);
        }
        contrib = 2.f * s * a.w * b.w;   // pair counted twice in full matrix
    }

    // block reduce -> one double atomic per block
    #pragma unroll
    for (int off = 16; off; off >>= 1)
        contrib += __shfl_down_sync(0xFFFFFFFFu, contrib, off);
    int warp = threadIdx.x >> 5;
    if ((threadIdx.x & 31) == 0) sh_red[warp] = (double)contrib;
    __syncthreads();
    if (threadIdx.x < 32) {
        double v = (threadIdx.x < (blockDim.x >> 5)) ? sh_red[threadIdx.x] : 0.0;
        #pragma unroll
        for (int off = 8; off; off >>= 1)
            v += __shfl_down_sync(0xFFFFFFFFu, v, off);
        if (threadIdx.x == 0 && v != 0.0)
            atomicAdd(&g_acc_real, v);
    }
}

// -------- reciprocal: one warp per k-vector, half-space * 2 --------
__global__ void k_recip(int n)
{
    int gw   = blockIdx.x * (blockDim.x >> 5) + (threadIdx.x >> 5);
    int lane = threadIdx.x & 31;
    if (gw >= NKHALF) return;

    int gz = gw % NKDIM;
    int gy = (gw / NKDIM) % NKDIM;
    int gx = gw / (NKDIM * NKDIM);
    float fx = (float)(gx - 8), fy = (float)(gy - 8), fz = (float)(gz - 8);

    float kx = fx*g_recipm[0] + fy*g_recipm[3] + fz*g_recipm[6];
    float ky = fx*g_recipm[1] + fy*g_recipm[4] + fz*g_recipm[7];
    float kz = fx*g_recipm[2] + fy*g_recipm[5] + fz*g_recipm[8];
    float k2 = fmaf(kx, kx, fmaf(ky, ky, kz*kz));
    if (!(k2 > 1e-16f && k2 < g_cut2_recip)) return;   // uniform per warp

    float eta = g_eta;
    float wk  = __fdividef(__expf(-0.5f * eta * eta * k2), k2);

    float qc = 0.f, qs = 0.f;
    for (int i = lane; i < n; i += 32) {
        float4 p = g_posq[i];
        float th = fmaf(kx, p.x, fmaf(ky, p.y, kz*p.z));
        float sn, cs;
        __sincosf(th, &sn, &cs);
        qc = fmaf(p.w, cs, qc);
        qs = fmaf(p.w, sn, qs);
    }
    #pragma unroll
    for (int off = 16; off; off >>= 1) {
        qc += __shfl_down_sync(0xFFFFFFFFu, qc, off);
        qs += __shfl_down_sync(0xFFFFFFFFu, qs, off);
    }
    if (lane == 0)
        atomicAdd(&g_acc_recip, (double)(2.f * wk * fmaf(qc, qc, qs*qs)));
}

// -------- finalize: self + diagonal real-space + combine --------
__global__ void k_fin(float* __restrict__ out, int n)
{
    __shared__ double sh[8];
    float eta = g_eta;
    float t0  = -sqrtf(2.f / 3.14159265358979323846f) / eta;
    float c0  = rsqrtf(3.14159265358979323846f);
    float inv_s2eta = g_inv_s2eta;
    float cut2 = g_cut2_real;

    float acc = 0.f;
    for (int i = threadIdx.x; i < n; i += blockDim.x) {
        float q = g_posq[i].w;
        // self term
        float v = t0 + c0 / g_sig[i];
        // diagonal real-space (nonzero only if any |shift| < cutoff)
        float invgam = g_gamtab[g_type[i]*NT + g_type[i]];
        #pragma unroll
        for (int m = 0; m < NSHIFT; m++) {
            float r2 = g_shift[m].w;
            if (r2 > 1e-16f && r2 < cut2) {
                float rinv = rsqrtf(r2);
                float r    = r2 * rinv;
                v = fmaf(erfc_fast(r * inv_s2eta) - erfc_fast(r * invgam), rinv, v);
            }
        }
        acc = fmaf(q*q, v, acc);
    }
    #pragma unroll
    for (int off = 16; off; off >>= 1)
        acc += __shfl_down_sync(0xFFFFFFFFu, acc, off);
    int warp = threadIdx.x >> 5;
    if ((threadIdx.x & 31) == 0) sh[warp] = (double)acc;
    __syncthreads();
    if (threadIdx.x == 0) {
        double diagsum = 0.0;
        int nw = (blockDim.x + 31) >> 5;
        for (int w = 0; w < nw; w++) diagsum += sh[w];
        const double COEF = 14.399645478425668;
        const double FOUR_PI = 12.566370614359172953850573533118;
        double e = 0.5 * COEF * (g_acc_real + diagsum
                                 + (FOUR_PI / g_vol) * g_acc_recip);
        out[0] = (float)e;
    }
}

extern "C" void kernel_launch(void* const* d_in, const int* in_sizes, int n_in,
                              void* d_out, int out_size)
{
    const float* pos     = (const float*)d_in[0];
    const float* cell    = (const float*)d_in[1];
    const float* charges = (const float*)d_in[2];
    const float* sigtab  = (const float*)d_in[3];
    const int*   species = (const int*)  d_in[4];

    int n = in_sizes[0] / 3;
    int npairs = n * (n - 1) / 2;

    k_setup<<<1, 1>>>(cell, sigtab, n);
    k_prep<<<(n + 255) / 256, 256>>>(pos, charges, sigtab, species, n);
    k_real<<<(npairs + 511) / 512, 512>>>(n, npairs);
    k_recip<<<(NKHALF * 32 + 255) / 256, 256>>>(n);
    k_fin<<<1, 256>>>((float*)d_out, n);
}

// round 4
// speedup vs baseline: 3.9836x; 3.9836x over previous
#include <cuda_runtime.h>
#include <cuda_bf16.h>
#include <math.h>

#define MAXN   1024
#define NSHIFT 27          // nshift_real = 1 -> 3^3
#define NKDIM  17          // nshift_recip = 8 -> 17 per dim
#define NKHALF 2456        // (17^3 - 1) / 2 ; inversion symmetry
#define NT     10          // NTYPES

// -------- device globals (scratch) --------
__device__ float4 g_posq[MAXN];          // x,y,z,q
__device__ float  g_sig[MAXN];
__device__ int    g_type[MAXN];
__device__ float  g_gamtab[NT*NT];       // 1/(sqrt(2)*gamma_ij)
__device__ float4 g_shift[NSHIFT];       // xyz = shift, w = |shift|^2
__device__ float  g_recipm[9];           // 2*pi*inv(cell)^T rows
__device__ float  g_eta, g_inv_s2eta, g_cut2_real, g_cut2_recip;
__device__ float  g_vol;
__device__ double g_acc_real, g_acc_recip;

// fast erfc: Abramowitz & Stegun 7.1.26, |abs err| <= 1.5e-7
__device__ __forceinline__ float erfc_fast(float x)
{
    float t = __fdividef(1.0f, fmaf(0.3275911f, x, 1.0f));
    float p = t * fmaf(t, fmaf(t, fmaf(t, fmaf(t, 1.061405429f, -1.453152027f),
                        1.421413741f), -0.284496736f), 0.254829592f);
    return p * __expf(-x * x);
}

// -------- fused setup + prep: ONE block of 768 threads, all fp32 --------
__global__ void __launch_bounds__(768) k_setup(
    const float* __restrict__ cell,  const float* __restrict__ sigtab,
    const float* __restrict__ pos,   const float* __restrict__ charges,
    const int*   __restrict__ species, int n)
{
    int tid = threadIdx.x;

    // per-atom pack (independent of everything else)
    if (tid < n) {
        g_posq[tid] = make_float4(pos[3*tid], pos[3*tid+1], pos[3*tid+2], charges[tid]);
        int sp = species[tid];
        g_sig[tid]  = sigtab[sp];
        g_type[tid] = sp;
    }

    // type-pair table: 100 parallel threads, fp32
    if (tid < NT * NT) {
        float sa = sigtab[tid / NT], sb = sigtab[tid % NT];
        g_gamtab[tid] = rsqrtf(2.0f * fmaf(sa, sa, sb * sb));
    }

    // 27 shifts: parallel threads
    if (tid < NSHIFT) {
        float sx = (float)(tid / 9 - 1);
        float sy = (float)((tid / 3) % 3 - 1);
        float sz = (float)(tid % 3 - 1);
        float x = sx*cell[0] + sy*cell[3] + sz*cell[6];
        float y = sx*cell[1] + sy*cell[4] + sz*cell[7];
        float z = sx*cell[2] + sy*cell[5] + sz*cell[8];
        g_shift[tid] = make_float4(x, y, z, fmaf(x,x,fmaf(y,y,z*z)));
    }

    if (tid == 1) { g_acc_real = 0.0; g_acc_recip = 0.0; }

    // scalars + reciprocal matrix: thread 0, fp32 (matches fp32 reference)
    if (tid == 0) {
        float c00 = cell[0], c01 = cell[1], c02 = cell[2];
        float c10 = cell[3], c11 = cell[4], c12 = cell[5];
        float c20 = cell[6], c21 = cell[7], c22 = cell[8];

        float cof00 =  (c11*c22 - c12*c21);
        float cof01 = -(c10*c22 - c12*c20);
        float cof02 =  (c10*c21 - c11*c20);
        float cof10 = -(c01*c22 - c02*c21);
        float cof11 =  (c00*c22 - c02*c20);
        float cof12 = -(c00*c21 - c01*c20);
        float cof20 =  (c01*c12 - c02*c11);
        float cof21 = -(c00*c12 - c02*c10);
        float cof22 =  (c00*c11 - c01*c10);

        float det = c00*cof00 + c01*cof01 + c02*cof02;
        float vol = fabsf(det);
        g_vol = vol;

        const float TWO_PI = 6.2831853071795864769f;
        float eta = powf(vol * vol / (float)n, 1.0f / 6.0f) * rsqrtf(TWO_PI);
        const float SQRT_2LOG = 6.0697086f;   // sqrt(-2*ln(1e-8))
        float cut_r = SQRT_2LOG * eta;
        float cut_k = SQRT_2LOG / eta;

        g_eta        = eta;
        g_inv_s2eta  = 1.0f / (1.4142135623730951f * eta);
        g_cut2_real  = cut_r * cut_r;
        g_cut2_recip = cut_k * cut_k;

        float inv_det = 1.0f / det;
        g_recipm[0] = TWO_PI * cof00 * inv_det;
        g_recipm[1] = TWO_PI * cof01 * inv_det;
        g_recipm[2] = TWO_PI * cof02 * inv_det;
        g_recipm[3] = TWO_PI * cof10 * inv_det;
        g_recipm[4] = TWO_PI * cof11 * inv_det;
        g_recipm[5] = TWO_PI * cof12 * inv_det;
        g_recipm[6] = TWO_PI * cof20 * inv_det;
        g_recipm[7] = TWO_PI * cof21 * inv_det;
        g_recipm[8] = TWO_PI * cof22 * inv_det;
    }
}

// -------- real-space: strictly-lower-triangular pairs, mask compaction --------
__global__ void __launch_bounds__(512) k_real(int n, int npairs)
{
    __shared__ float4 sh_shift[NSHIFT];
    __shared__ double sh_red[16];
    if (threadIdx.x < NSHIFT) sh_shift[threadIdx.x] = g_shift[threadIdx.x];
    __syncthreads();

    int t = blockIdx.x * blockDim.x + threadIdx.x;
    float contrib = 0.f;

    if (t < npairs) {
        // decode t -> (i, j), j < i.  8t+1 < 2^24 -> exact fp32
        int i = (int)((1.0f + sqrtf(1.0f + 8.0f * (float)t)) * 0.5f);
        while (i * (i - 1) / 2 > t) i--;
        while ((i + 1) * i / 2 <= t) i++;
        int j = t - i * (i - 1) / 2;

        float4 a = g_posq[i];
        float4 b = g_posq[j];
        float dx = b.x - a.x, dy = b.y - a.y, dz = b.z - a.z;
        float inv_s2gam = g_gamtab[g_type[i]*NT + g_type[j]];
        float inv_s2eta = g_inv_s2eta;
        float cut2      = g_cut2_real;

        // pass 1: cheap mask build (FMA + SETP only)
        unsigned mask = 0u;
        #pragma unroll
        for (int m = 0; m < NSHIFT; m++) {
            float ddx = dx + sh_shift[m].x;
            float ddy = dy + sh_shift[m].y;
            float ddz = dz + sh_shift[m].z;
            float r2  = fmaf(ddx, ddx, fmaf(ddy, ddy, ddz*ddz));
            if (r2 > 1e-16f && r2 < cut2) mask |= (1u << m);
        }

        // pass 2: expensive math only on hits (warp runs max-hits times)
        float s = 0.f;
        while (mask) {
            int m = __ffs(mask) - 1;
            mask &= mask - 1;
            float4 sm = sh_shift[m];
            float ddx = dx + sm.x;
            float ddy = dy + sm.y;
            float ddz = dz + sm.z;
            float r2  = fmaf(ddx, ddx, fmaf(ddy, ddy, ddz*ddz));
            float rinv = rsqrtf(r2);
            float r    = r2 * rinv;
            s = fmaf(erfc_fast(r * inv_s2eta) - erfc_fast(r * inv_s2gam), rinv, s);
        }
        contrib = 2.f * s * a.w * b.w;   // off-diagonal counted twice
    }

    // block reduce -> one double atomic per block
    #pragma unroll
    for (int off = 16; off; off >>= 1)
        contrib += __shfl_down_sync(0xFFFFFFFFu, contrib, off);
    int warp = threadIdx.x >> 5;
    if ((threadIdx.x & 31) == 0) sh_red[warp] = (double)contrib;
    __syncthreads();
    if (threadIdx.x < 32) {
        double v = (threadIdx.x < (blockDim.x >> 5)) ? sh_red[threadIdx.x] : 0.0;
        #pragma unroll
        for (int off = 8; off; off >>= 1)
            v += __shfl_down_sync(0xFFFFFFFFu, v, off);
        if (threadIdx.x == 0 && v != 0.0)
            atomicAdd(&g_acc_real, v);
    }
}

// -------- reciprocal: 2 warps per k, smem positions, ILP-unrolled --------
__global__ void __launch_bounds__(512) k_recip(int n)
{
    __shared__ float4 sp[MAXN];
    __shared__ float  s_qc[16], s_qs[16];
    for (int i = threadIdx.x; i < n; i += blockDim.x) sp[i] = g_posq[i];
    __syncthreads();

    int wid  = threadIdx.x >> 5;
    int lane = threadIdx.x & 31;
    int gwarp = blockIdx.x * 16 + wid;
    int kidx  = gwarp >> 1;
    int half  = gwarp & 1;

    float kx = 0.f, ky = 0.f, kz = 0.f, wk = 0.f;
    bool active = (kidx < NKHALF);
    if (active) {
        int gz = kidx % NKDIM;
        int gy = (kidx / NKDIM) % NKDIM;
        int gx = kidx / (NKDIM * NKDIM);
        float fx = (float)(gx - 8), fy = (float)(gy - 8), fz = (float)(gz - 8);
        kx = fx*g_recipm[0] + fy*g_recipm[3] + fz*g_recipm[6];
        ky = fx*g_recipm[1] + fy*g_recipm[4] + fz*g_recipm[7];
        kz = fx*g_recipm[2] + fy*g_recipm[5] + fz*g_recipm[8];
        float k2 = fmaf(kx, kx, fmaf(ky, ky, kz*kz));
        if (k2 > 1e-16f && k2 < g_cut2_recip) {
            float eta = g_eta;
            wk = __fdividef(__expf(-0.5f * eta * eta * k2), k2);
        } else {
            active = false;
        }
    }

    float qc = 0.f, qs = 0.f;
    if (active) {
        // 4 independent accumulator chains over this warp's atom half
        float qc0=0.f,qc1=0.f,qc2=0.f,qc3=0.f, qs0=0.f,qs1=0.f,qs2=0.f,qs3=0.f;
        int i = lane + half * 32;
        #pragma unroll 1
        for (; i + 192 < n; i += 256) {
            float4 p0 = sp[i], p1 = sp[i+64], p2 = sp[i+128], p3 = sp[i+192];
            float sn, cs;
            __sincosf(fmaf(kx,p0.x,fmaf(ky,p0.y,kz*p0.z)), &sn, &cs);
            qc0 = fmaf(p0.w, cs, qc0); qs0 = fmaf(p0.w, sn, qs0);
            __sincosf(fmaf(kx,p1.x,fmaf(ky,p1.y,kz*p1.z)), &sn, &cs);
            qc1 = fmaf(p1.w, cs, qc1); qs1 = fmaf(p1.w, sn, qs1);
            __sincosf(fmaf(kx,p2.x,fmaf(ky,p2.y,kz*p2.z)), &sn, &cs);
            qc2 = fmaf(p2.w, cs, qc2); qs2 = fmaf(p2.w, sn, qs2);
            __sincosf(fmaf(kx,p3.x,fmaf(ky,p3.y,kz*p3.z)), &sn, &cs);
            qc3 = fmaf(p3.w, cs, qc3); qs3 = fmaf(p3.w, sn, qs3);
        }
        for (; i < n; i += 64) {
            float4 p = sp[i];
            float sn, cs;
            __sincosf(fmaf(kx,p.x,fmaf(ky,p.y,kz*p.z)), &sn, &cs);
            qc0 = fmaf(p.w, cs, qc0); qs0 = fmaf(p.w, sn, qs0);
        }
        qc = (qc0 + qc1) + (qc2 + qc3);
        qs = (qs0 + qs1) + (qs2 + qs3);
    }

    #pragma unroll
    for (int off = 16; off; off >>= 1) {
        qc += __shfl_down_sync(0xFFFFFFFFu, qc, off);
        qs += __shfl_down_sync(0xFFFFFFFFu, qs, off);
    }
    if (lane == 0) { s_qc[wid] = qc; s_qs[wid] = qs; }
    __syncthreads();
    if (active && half == 0 && lane == 0) {
        float C = s_qc[wid] + s_qc[wid + 1];
        float S = s_qs[wid] + s_qs[wid + 1];
        atomicAdd(&g_acc_recip, (double)(2.f * wk * fmaf(C, C, S*S)));
    }
}

// -------- finalize: self + diagonal real-space + combine --------
__global__ void k_fin(float* __restrict__ out, int n)
{
    __shared__ double sh[8];
    float eta = g_eta;
    float t0  = -sqrtf(2.f / 3.14159265358979323846f) / eta;
    float c0  = rsqrtf(3.14159265358979323846f);
    float inv_s2eta = g_inv_s2eta;
    float cut2 = g_cut2_real;

    float acc = 0.f;
    for (int i = threadIdx.x; i < n; i += blockDim.x) {
        float q = g_posq[i].w;
        float v = t0 + c0 / g_sig[i];                       // self
        float invgam = g_gamtab[g_type[i]*NT + g_type[i]];  // diagonal real
        #pragma unroll
        for (int m = 0; m < NSHIFT; m++) {
            float r2 = g_shift[m].w;
            if (r2 > 1e-16f && r2 < cut2) {
                float rinv = rsqrtf(r2);
                float r    = r2 * rinv;
                v = fmaf(erfc_fast(r * inv_s2eta) - erfc_fast(r * invgam), rinv, v);
            }
        }
        acc = fmaf(q*q, v, acc);
    }
    #pragma unroll
    for (int off = 16; off; off >>= 1)
        acc += __shfl_down_sync(0xFFFFFFFFu, acc, off);
    int warp = threadIdx.x >> 5;
    if ((threadIdx.x & 31) == 0) sh[warp] = (double)acc;
    __syncthreads();
    if (threadIdx.x == 0) {
        double diagsum = 0.0;
        int nw = (blockDim.x + 31) >> 5;
        for (int w = 0; w < nw; w++) diagsum += sh[w];
        const double COEF = 14.399645478425668;
        const double FOUR_PI = 12.566370614359172953850573533118;
        double e = 0.5 * COEF * (g_acc_real + diagsum
                                 + (FOUR_PI / (double)g_vol) * g_acc_recip);
        out[0] = (float)e;
    }
}

extern "C" void kernel_launch(void* const* d_in, const int* in_sizes, int n_in,
                              void* d_out, int out_size)
{
    const float* pos     = (const float*)d_in[0];
    const float* cell    = (const float*)d_in[1];
    const float* charges = (const float*)d_in[2];
    const float* sigtab  = (const float*)d_in[3];
    const int*   species = (const int*)  d_in[4];

    int n = in_sizes[0] / 3;
    int npairs = n * (n - 1) / 2;

    k_setup<<<1, 768>>>(cell, sigtab, pos, charges, species, n);
    k_real<<<(npairs + 511) / 512, 512>>>(n, npairs);
    k_recip<<<(NKHALF * 2 + 15) / 16, 512>>>(n);
    k_fin<<<1, 256>>>((float*)d_out, n);
}

// round 5
// speedup vs baseline: 4.8034x; 1.2058x over previous
#include <cuda_runtime.h>
#include <cuda_bf16.h>
#include <math.h>

#define MAXN   1024
#define NSHIFT 27          // nshift_real = 1 -> 3^3
#define NKDIM  17          // nshift_recip = 8 -> 17 per dim
#define NKHALF 2456        // (17^3 - 1) / 2 ; inversion symmetry
#define NB_RECIP 307       // ceil(NKHALF * 2 warps / 16 warps per block)
#define NT     10

// -------- device globals (scratch) --------
__device__ float4 g_posq[MAXN];          // x,y,z,q
__device__ float  g_sig[MAXN];
__device__ float4 g_shift[NSHIFT];       // xyz = shift, w = |shift|^2
__device__ float  g_recipm[9];           // 2*pi*inv(cell)^T rows
__device__ float  g_eta, g_inv_s2eta, g_cut2_real, g_cut2_recip;
__device__ float  g_vol;
__device__ double g_acc_real, g_acc_recip, g_acc_self;
__device__ unsigned g_ticket;

// fast erfc: Abramowitz & Stegun 7.1.26, |abs err| <= 1.5e-7
__device__ __forceinline__ float erfc_fast(float x)
{
    float t = __fdividef(1.0f, fmaf(0.3275911f, x, 1.0f));
    float p = t * fmaf(t, fmaf(t, fmaf(t, fmaf(t, 1.061405429f, -1.453152027f),
                        1.421413741f), -0.284496736f), 0.254829592f);
    return p * __expf(-x * x);
}

// -------- fused setup + pack: ONE block of 768 threads, all fp32 --------
__global__ void __launch_bounds__(768) k_setup(
    const float* __restrict__ cell,  const float* __restrict__ sigtab,
    const float* __restrict__ pos,   const float* __restrict__ charges,
    const int*   __restrict__ species, int n)
{
    int tid = threadIdx.x;

    if (tid < n) {
        g_posq[tid] = make_float4(pos[3*tid], pos[3*tid+1], pos[3*tid+2], charges[tid]);
        g_sig[tid]  = sigtab[species[tid]];
    }

    if (tid < NSHIFT) {
        float sx = (float)(tid / 9 - 1);
        float sy = (float)((tid / 3) % 3 - 1);
        float sz = (float)(tid % 3 - 1);
        float x = sx*cell[0] + sy*cell[3] + sz*cell[6];
        float y = sx*cell[1] + sy*cell[4] + sz*cell[7];
        float z = sx*cell[2] + sy*cell[5] + sz*cell[8];
        g_shift[tid] = make_float4(x, y, z, fmaf(x,x,fmaf(y,y,z*z)));
    }

    if (tid == 1) { g_acc_real = 0.0; g_acc_recip = 0.0; g_acc_self = 0.0; g_ticket = 0u; }

    if (tid == 0) {
        float c00 = cell[0], c01 = cell[1], c02 = cell[2];
        float c10 = cell[3], c11 = cell[4], c12 = cell[5];
        float c20 = cell[6], c21 = cell[7], c22 = cell[8];

        float cof00 =  (c11*c22 - c12*c21);
        float cof01 = -(c10*c22 - c12*c20);
        float cof02 =  (c10*c21 - c11*c20);
        float cof10 = -(c01*c22 - c02*c21);
        float cof11 =  (c00*c22 - c02*c20);
        float cof12 = -(c00*c21 - c01*c20);
        float cof20 =  (c01*c12 - c02*c11);
        float cof21 = -(c00*c12 - c02*c10);
        float cof22 =  (c00*c11 - c01*c10);

        float det = c00*cof00 + c01*cof01 + c02*cof02;
        float vol = fabsf(det);
        g_vol = vol;

        const float TWO_PI = 6.2831853071795864769f;
        float eta = powf(vol * vol / (float)n, 1.0f / 6.0f) * rsqrtf(TWO_PI);
        const float SQRT_2LOG = 6.0697086f;   // sqrt(-2*ln(1e-8))
        float cut_r = SQRT_2LOG * eta;
        float cut_k = SQRT_2LOG / eta;

        g_eta        = eta;
        g_inv_s2eta  = 1.0f / (1.4142135623730951f * eta);
        g_cut2_real  = cut_r * cut_r;
        g_cut2_recip = cut_k * cut_k;

        float inv_det = 1.0f / det;
        g_recipm[0] = TWO_PI * cof00 * inv_det;
        g_recipm[1] = TWO_PI * cof01 * inv_det;
        g_recipm[2] = TWO_PI * cof02 * inv_det;
        g_recipm[3] = TWO_PI * cof10 * inv_det;
        g_recipm[4] = TWO_PI * cof11 * inv_det;
        g_recipm[5] = TWO_PI * cof12 * inv_det;
        g_recipm[6] = TWO_PI * cof20 * inv_det;
        g_recipm[7] = TWO_PI * cof21 * inv_det;
        g_recipm[8] = TWO_PI * cof22 * inv_det;
    }
}

// ==================== fused main kernel ====================
// blocks [0, nb_real)                  : real-space pairs
// blocks [nb_real, nb_real+NB_RECIP)   : reciprocal k-vectors
// block  nb_real+NB_RECIP              : self + diagonal real-space
// last block to finish                 : finalize + write out
__global__ void __launch_bounds__(512) k_main(int n, int npairs, int nb_real,
                                              float* __restrict__ out)
{
    __shared__ float4 sbuf[MAXN];       // recip: posq ; real/self: shifts in [0,27)
    __shared__ double sred[16];
    __shared__ float  s_qc[16], s_qs[16], s_wk[16];

    int bid = blockIdx.x;
    int tid = threadIdx.x;

    if (bid < nb_real) {
        // ---------------- real-space pairs ----------------
        if (tid < NSHIFT) sbuf[tid] = g_shift[tid];
        __syncthreads();

        int t = bid * 512 + tid;
        float contrib = 0.f;
        if (t < npairs) {
            // decode t -> (i, j), j < i ; 8t+1 < 2^24 exact in fp32
            int i = (int)((1.0f + sqrtf(1.0f + 8.0f * (float)t)) * 0.5f);
            while (i * (i - 1) / 2 > t) i--;
            while ((i + 1) * i / 2 <= t) i++;
            int j = t - i * (i - 1) / 2;

            float4 a = g_posq[i];
            float4 b = g_posq[j];
            float dx = b.x - a.x, dy = b.y - a.y, dz = b.z - a.z;
            float si = g_sig[i], sj = g_sig[j];
            float inv_s2gam = rsqrtf(2.0f * fmaf(si, si, sj * sj));
            float inv_s2eta = g_inv_s2eta;
            float cut2      = g_cut2_real;

            unsigned mask = 0u;
            #pragma unroll
            for (int m = 0; m < NSHIFT; m++) {
                float ddx = dx + sbuf[m].x;
                float ddy = dy + sbuf[m].y;
                float ddz = dz + sbuf[m].z;
                float r2  = fmaf(ddx, ddx, fmaf(ddy, ddy, ddz*ddz));
                if (r2 > 1e-16f && r2 < cut2) mask |= (1u << m);
            }
            float s = 0.f;
            while (mask) {
                int m = __ffs(mask) - 1;
                mask &= mask - 1;
                float4 sm = sbuf[m];
                float ddx = dx + sm.x;
                float ddy = dy + sm.y;
                float ddz = dz + sm.z;
                float r2  = fmaf(ddx, ddx, fmaf(ddy, ddy, ddz*ddz));
                float rinv = rsqrtf(r2);
                float r    = r2 * rinv;
                s = fmaf(erfc_fast(r * inv_s2eta) - erfc_fast(r * inv_s2gam), rinv, s);
            }
            contrib = 2.f * s * a.w * b.w;
        }

        #pragma unroll
        for (int off = 16; off; off >>= 1)
            contrib += __shfl_down_sync(0xFFFFFFFFu, contrib, off);
        int warp = tid >> 5;
        if ((tid & 31) == 0) sred[warp] = (double)contrib;
        __syncthreads();
        if (tid < 32) {
            double v = (tid < 16) ? sred[tid] : 0.0;
            #pragma unroll
            for (int off = 8; off; off >>= 1)
                v += __shfl_down_sync(0xFFFFFFFFu, v, off);
            if (tid == 0 && v != 0.0) atomicAdd(&g_acc_real, v);
        }
    }
    else if (bid < nb_real + NB_RECIP) {
        // ---------------- reciprocal ----------------
        for (int i = tid; i < n; i += 512) sbuf[i] = g_posq[i];
        __syncthreads();

        int wid  = tid >> 5;
        int lane = tid & 31;
        int gwarp = (bid - nb_real) * 16 + wid;
        int kidx  = gwarp >> 1;
        int half  = gwarp & 1;

        float kx = 0.f, ky = 0.f, kz = 0.f, wk = 0.f;
        bool active = (kidx < NKHALF);
        if (active) {
            int gz = kidx % NKDIM;
            int gy = (kidx / NKDIM) % NKDIM;
            int gx = kidx / (NKDIM * NKDIM);
            float fx = (float)(gx - 8), fy = (float)(gy - 8), fz = (float)(gz - 8);
            kx = fx*g_recipm[0] + fy*g_recipm[3] + fz*g_recipm[6];
            ky = fx*g_recipm[1] + fy*g_recipm[4] + fz*g_recipm[7];
            kz = fx*g_recipm[2] + fy*g_recipm[5] + fz*g_recipm[8];
            float k2 = fmaf(kx, kx, fmaf(ky, ky, kz*kz));
            if (k2 > 1e-16f && k2 < g_cut2_recip) {
                float eta = g_eta;
                wk = __fdividef(__expf(-0.5f * eta * eta * k2), k2);
            } else active = false;
        }

        float qc = 0.f, qs = 0.f;
        if (active) {
            float qc0=0.f,qc1=0.f,qc2=0.f,qc3=0.f, qs0=0.f,qs1=0.f,qs2=0.f,qs3=0.f;
            int i = lane + half * 32;
            #pragma unroll 1
            for (; i + 192 < n; i += 256) {
                float4 p0 = sbuf[i], p1 = sbuf[i+64], p2 = sbuf[i+128], p3 = sbuf[i+192];
                float sn, cs;
                __sincosf(fmaf(kx,p0.x,fmaf(ky,p0.y,kz*p0.z)), &sn, &cs);
                qc0 = fmaf(p0.w, cs, qc0); qs0 = fmaf(p0.w, sn, qs0);
                __sincosf(fmaf(kx,p1.x,fmaf(ky,p1.y,kz*p1.z)), &sn, &cs);
                qc1 = fmaf(p1.w, cs, qc1); qs1 = fmaf(p1.w, sn, qs1);
                __sincosf(fmaf(kx,p2.x,fmaf(ky,p2.y,kz*p2.z)), &sn, &cs);
                qc2 = fmaf(p2.w, cs, qc2); qs2 = fmaf(p2.w, sn, qs2);
                __sincosf(fmaf(kx,p3.x,fmaf(ky,p3.y,kz*p3.z)), &sn, &cs);
                qc3 = fmaf(p3.w, cs, qc3); qs3 = fmaf(p3.w, sn, qs3);
            }
            for (; i < n; i += 64) {
                float4 p = sbuf[i];
                float sn, cs;
                __sincosf(fmaf(kx,p.x,fmaf(ky,p.y,kz*p.z)), &sn, &cs);
                qc0 = fmaf(p.w, cs, qc0); qs0 = fmaf(p.w, sn, qs0);
            }
            qc = (qc0 + qc1) + (qc2 + qc3);
            qs = (qs0 + qs1) + (qs2 + qs3);
        }

        #pragma unroll
        for (int off = 16; off; off >>= 1) {
            qc += __shfl_down_sync(0xFFFFFFFFu, qc, off);
            qs += __shfl_down_sync(0xFFFFFFFFu, qs, off);
        }
        if (lane == 0) { s_qc[wid] = qc; s_qs[wid] = qs; s_wk[wid] = wk; }
        __syncthreads();
        // combine 8 k-values of this block -> one atomic
        if (tid < 8) {
            float C = s_qc[2*tid] + s_qc[2*tid+1];
            float S = s_qs[2*tid] + s_qs[2*tid+1];
            sred[tid] = (double)(2.f * s_wk[2*tid] * fmaf(C, C, S*S));
        }
        __syncthreads();
        if (tid == 0) {
            double v = sred[0]+sred[1]+sred[2]+sred[3]+sred[4]+sred[5]+sred[6]+sred[7];
            if (v != 0.0) atomicAdd(&g_acc_recip, v);
        }
    }
    else {
        // ---------------- self + diagonal real-space ----------------
        if (tid < NSHIFT) sbuf[tid] = g_shift[tid];
        __syncthreads();

        float eta = g_eta;
        float t0  = -sqrtf(2.f / 3.14159265358979323846f) / eta;
        float c0  = rsqrtf(3.14159265358979323846f);
        float inv_s2eta = g_inv_s2eta;
        float cut2 = g_cut2_real;

        float acc = 0.f;
        for (int i = tid; i < n; i += 512) {
            float q   = g_posq[i].w;
            float sig = g_sig[i];
            float v   = t0 + c0 / sig;
            float invgam = rsqrtf(4.0f * sig * sig) ;  // 1/(sqrt(2)*sqrt(2 sig^2))
            #pragma unroll
            for (int m = 0; m < NSHIFT; m++) {
                float r2 = sbuf[m].w;
                if (r2 > 1e-16f && r2 < cut2) {
                    float rinv = rsqrtf(r2);
                    float r    = r2 * rinv;
                    v = fmaf(erfc_fast(r * inv_s2eta) - erfc_fast(r * invgam), rinv, v);
                }
            }
            acc = fmaf(q*q, v, acc);
        }
        #pragma unroll
        for (int off = 16; off; off >>= 1)
            acc += __shfl_down_sync(0xFFFFFFFFu, acc, off);
        int warp = tid >> 5;
        if ((tid & 31) == 0) sred[warp] = (double)acc;
        __syncthreads();
        if (tid == 0) {
            double v = 0.0;
            for (int w = 0; w < 16; w++) v += sred[w];
            atomicAdd(&g_acc_self, v);
        }
    }

    // ---------------- last block to finish finalizes ----------------
    __syncthreads();
    if (tid == 0) {
        __threadfence();
        unsigned ticket = atomicAdd(&g_ticket, 1u);
        if (ticket == gridDim.x - 1u) {
            const double COEF    = 14.399645478425668;
            const double FOUR_PI = 12.566370614359172953850573533118;
            double e = 0.5 * COEF * (g_acc_real + g_acc_self
                                     + (FOUR_PI / (double)g_vol) * g_acc_recip);
            out[0] = (float)e;
        }
    }
}

extern "C" void kernel_launch(void* const* d_in, const int* in_sizes, int n_in,
                              void* d_out, int out_size)
{
    const float* pos     = (const float*)d_in[0];
    const float* cell    = (const float*)d_in[1];
    const float* charges = (const float*)d_in[2];
    const float* sigtab  = (const float*)d_in[3];
    const int*   species = (const int*)  d_in[4];

    int n = in_sizes[0] / 3;
    int npairs  = n * (n - 1) / 2;
    int nb_real = (npairs + 511) / 512;
    int grid    = nb_real + NB_RECIP + 1;

    k_setup<<<1, 768>>>(cell, sigtab, pos, charges, species, n);
    k_main<<<grid, 512>>>(n, npairs, nb_real, (float*)d_out);
}